// round 1
// baseline (speedup 1.0000x reference)
#include <cuda_runtime.h>
#include <math_constants.h>

// ---------------------------------------------------------------------------
// TSFuzzyLayer: per-edge fuzzy attention + global softmax over edge_sg_ID set
// inputs (metadata order):
//   0: feat  [N_NODES,4] f32
//   1: src   [N_EDGES]   i32
//   2: dst   [N_EDGES]   i32
//   3: edge_sg_ID [1,N_SG] i32
//   4: sub_systems_mat [2,9] f32
//   5: sub_systems_bias [9]  f32
// output: attention [N_EDGES,1,1] f32
// ---------------------------------------------------------------------------

#define NPART 1024

__device__ float g_pmax[NPART];
__device__ float g_psum[NPART];
__device__ float g_stats[2];   // [0]=global max, [1]=1/sum

// -------------------------- pass 1: per-edge attention ----------------------
__global__ void __launch_bounds__(256) edge_attention_kernel(
    const float* __restrict__ feat,
    const int*   __restrict__ src,
    const int*   __restrict__ dst,
    const float* __restrict__ mat,    // 2x9 row-major
    const float* __restrict__ bias,   // 9
    float* __restrict__ out,
    int n_edges)
{
    __shared__ float sM0[9], sM1[9], sB[9];
    int t = threadIdx.x;
    if (t < 9)  sM0[t] = mat[t];
    else if (t < 18) sM1[t - 9] = mat[t];
    else if (t < 27) sB[t - 18] = bias[t - 18];
    __syncthreads();

    int e = blockIdx.x * blockDim.x + t;
    if (e >= n_edges) return;

    int si = src[e];
    int di = dst[e];
    float4 fs = *reinterpret_cast<const float4*>(feat + 4 * (long long)si);
    float4 fd = *reinterpret_cast<const float4*>(feat + 4 * (long long)di);

    float d0 = fd.x - fs.x;
    float d1 = fd.y - fs.y;
    float v0 = fd.z - fs.z;
    float v1 = fd.w - fs.w;

    float x1 = sqrtf(fmaf(d0, d0, d1 * d1));
    float vn = sqrtf(fmaf(v0, v0, v1 * v1));
    float dotv = fmaf(d0, v0, d1 * v1);
    float c = dotv / fmaf(x1, vn, 1e-8f);
    c = fminf(fmaxf(c, -1.0f + 1e-6f), 1.0f - 1e-6f);
    float x2 = acosf(c) * 57.29577951308232f;   // degrees

    const float inv2s1 = 1.0f / 1.125f;   // 1/(2*0.75^2)
    const float inv2s2 = 1.0f / 1800.0f;  // 1/(2*30^2)

    float m1[3], m2[3];
    {
        float a0 = x1 - 0.0f, a1 = x1 - 2.0f, a2 = x1 - 4.0f;
        m1[0] = __expf(-a0 * a0 * inv2s1);
        m1[1] = __expf(-a1 * a1 * inv2s1);
        m1[2] = __expf(-a2 * a2 * inv2s1);
        float b0 = x2 - 0.0f, b1 = x2 - 90.0f, b2 = x2 - 180.0f;
        m2[0] = __expf(-b0 * b0 * inv2s2);
        m2[1] = __expf(-b1 * b1 * inv2s2);
        m2[2] = __expf(-b2 * b2 * inv2s2);
    }

    float num = 0.0f, den = 0.0f;
    #pragma unroll
    for (int i = 0; i < 3; ++i) {
        #pragma unroll
        for (int j = 0; j < 3; ++j) {
            int r = i * 3 + j;
            float tm = fminf(m1[i], m2[j]);
            float cons = fmaf(x1, sM0[r], fmaf(x2, sM1[r], sB[r]));
            num = fmaf(tm, cons, num);
            den += tm;
        }
    }
    out[e] = num / den;
}

// --------------------- online (max,sum) combine helper ----------------------
__device__ __forceinline__ void combine_ms(float& m, float& s, float mo, float so)
{
    float mn = fmaxf(m, mo);
    if (mn == -CUDART_INF_F) { m = mn; s = 0.0f; return; }
    s = s * __expf(m - mn) + so * __expf(mo - mn);
    m = mn;
}

// ------------------- pass 2a: partial softmax reduction ---------------------
__global__ void __launch_bounds__(256) softmax_reduce_kernel(
    const float* __restrict__ out,
    const int*   __restrict__ idx,
    int n_sg)
{
    float m = -CUDART_INF_F, s = 0.0f;
    for (int i = blockIdx.x * blockDim.x + threadIdx.x; i < n_sg;
         i += gridDim.x * blockDim.x) {
        float v = out[idx[i]];
        if (v > m) {
            s = fmaf(s, __expf(m - v), 1.0f);
            m = v;
        } else {
            s += __expf(v - m);
        }
    }
    // warp reduce
    #pragma unroll
    for (int o = 16; o > 0; o >>= 1) {
        float mo = __shfl_xor_sync(0xFFFFFFFFu, m, o);
        float so = __shfl_xor_sync(0xFFFFFFFFu, s, o);
        combine_ms(m, s, mo, so);
    }
    __shared__ float sm[8], ss[8];
    int wid = threadIdx.x >> 5, lid = threadIdx.x & 31;
    if (lid == 0) { sm[wid] = m; ss[wid] = s; }
    __syncthreads();
    if (wid == 0) {
        m = (lid < 8) ? sm[lid] : -CUDART_INF_F;
        s = (lid < 8) ? ss[lid] : 0.0f;
        #pragma unroll
        for (int o = 4; o > 0; o >>= 1) {
            float mo = __shfl_xor_sync(0xFFFFFFFFu, m, o);
            float so = __shfl_xor_sync(0xFFFFFFFFu, s, o);
            combine_ms(m, s, mo, so);
        }
        if (lid == 0) {
            g_pmax[blockIdx.x] = m;
            g_psum[blockIdx.x] = s;
        }
    }
}

// -------------------- pass 2b: combine partials (1 block) -------------------
__global__ void __launch_bounds__(1024) softmax_combine_kernel()
{
    int t = threadIdx.x;
    float m = g_pmax[t];
    float s = g_psum[t];
    #pragma unroll
    for (int o = 16; o > 0; o >>= 1) {
        float mo = __shfl_xor_sync(0xFFFFFFFFu, m, o);
        float so = __shfl_xor_sync(0xFFFFFFFFu, s, o);
        combine_ms(m, s, mo, so);
    }
    __shared__ float sm[32], ss[32];
    int wid = t >> 5, lid = t & 31;
    if (lid == 0) { sm[wid] = m; ss[wid] = s; }
    __syncthreads();
    if (wid == 0) {
        m = sm[lid];
        s = ss[lid];
        #pragma unroll
        for (int o = 16; o > 0; o >>= 1) {
            float mo = __shfl_xor_sync(0xFFFFFFFFu, m, o);
            float so = __shfl_xor_sync(0xFFFFFFFFu, s, o);
            combine_ms(m, s, mo, so);
        }
        if (lid == 0) {
            g_stats[0] = m;
            g_stats[1] = 1.0f / s;
        }
    }
}

// ----------------------- pass 2c: normalize in place ------------------------
__global__ void __launch_bounds__(256) softmax_write_kernel(
    float* __restrict__ out,
    const int* __restrict__ idx,
    int n_sg)
{
    int i = blockIdx.x * blockDim.x + threadIdx.x;
    if (i >= n_sg) return;
    float M    = g_stats[0];
    float invS = g_stats[1];
    int j = idx[i];
    float v = out[j];
    out[j] = __expf(v - M) * invS;
}

// ---------------------------------------------------------------------------
extern "C" void kernel_launch(void* const* d_in, const int* in_sizes, int n_in,
                              void* d_out, int out_size)
{
    const float* feat = (const float*)d_in[0];
    const int*   src  = (const int*)  d_in[1];
    const int*   dst  = (const int*)  d_in[2];
    const int*   sgid = (const int*)  d_in[3];
    const float* mat  = (const float*)d_in[4];
    const float* bias = (const float*)d_in[5];
    float* out = (float*)d_out;

    int n_edges = in_sizes[1];
    int n_sg    = in_sizes[3];

    int blocks1 = (n_edges + 255) / 256;
    edge_attention_kernel<<<blocks1, 256>>>(feat, src, dst, mat, bias, out, n_edges);

    softmax_reduce_kernel<<<NPART, 256>>>(out, sgid, n_sg);
    softmax_combine_kernel<<<1, 1024>>>();

    int blocks2 = (n_sg + 255) / 256;
    softmax_write_kernel<<<blocks2, 256>>>(out, sgid, n_sg);
}

// round 2
// speedup vs baseline: 1.0534x; 1.0534x over previous
#include <cuda_runtime.h>
#include <math_constants.h>

// ---------------------------------------------------------------------------
// TSFuzzyLayer: per-edge fuzzy attention + global softmax over edge_sg_ID set
// inputs (metadata order):
//   0: feat  [N_NODES,4] f32
//   1: src   [N_EDGES]   i32
//   2: dst   [N_EDGES]   i32
//   3: edge_sg_ID [1,N_SG] i32
//   4: sub_systems_mat [2,9] f32
//   5: sub_systems_bias [9]  f32
// output: attention [N_EDGES,1,1] f32
// ---------------------------------------------------------------------------

#define NPART 1024

__device__ float g_pmax[NPART];
__device__ float g_psum[NPART];
__device__ float g_stats[2];   // [0]=global max, [1]=1/sum

// ---- fast acos in degrees (A&S 4.4.45, max err 6.7e-5 rad = 0.0038 deg) ----
__device__ __forceinline__ float acos_deg(float c)
{
    float a = fabsf(c);
    float p = fmaf(a, -0.0187293f, 0.0742610f);
    p = fmaf(a, p, -0.2121144f);
    p = fmaf(a, p, 1.5707288f);
    float r = sqrtf(1.0f - a) * p;          // acos(a), a in [0,1]
    float ac = (c < 0.0f) ? (CUDART_PI_F - r) : r;
    return ac * 57.29577951308232f;
}

// ---- per-edge attention math ----------------------------------------------
__device__ __forceinline__ float edge_attn(
    float4 fs, float4 fd,
    const float* __restrict__ sM0, const float* __restrict__ sM1,
    const float* __restrict__ sB)
{
    float d0 = fd.x - fs.x;
    float d1 = fd.y - fs.y;
    float v0 = fd.z - fs.z;
    float v1 = fd.w - fs.w;

    float x1 = sqrtf(fmaf(d0, d0, d1 * d1));
    float vn = sqrtf(fmaf(v0, v0, v1 * v1));
    float dotv = fmaf(d0, v0, d1 * v1);
    float c = __fdividef(dotv, fmaf(x1, vn, 1e-8f));
    c = fminf(fmaxf(c, -1.0f + 1e-6f), 1.0f - 1e-6f);
    float x2 = acos_deg(c);

    const float inv2s1 = 1.0f / 1.125f;   // 1/(2*0.75^2)
    const float inv2s2 = 1.0f / 1800.0f;  // 1/(2*30^2)

    float m1[3], m2[3];
    float a0 = x1, a1 = x1 - 2.0f, a2 = x1 - 4.0f;
    m1[0] = __expf(-a0 * a0 * inv2s1);
    m1[1] = __expf(-a1 * a1 * inv2s1);
    m1[2] = __expf(-a2 * a2 * inv2s1);
    float b0 = x2, b1 = x2 - 90.0f, b2 = x2 - 180.0f;
    m2[0] = __expf(-b0 * b0 * inv2s2);
    m2[1] = __expf(-b1 * b1 * inv2s2);
    m2[2] = __expf(-b2 * b2 * inv2s2);

    float num = 0.0f, den = 0.0f;
    #pragma unroll
    for (int i = 0; i < 3; ++i) {
        #pragma unroll
        for (int j = 0; j < 3; ++j) {
            int r = i * 3 + j;
            float tm = fminf(m1[i], m2[j]);
            float cons = fmaf(x1, sM0[r], fmaf(x2, sM1[r], sB[r]));
            num = fmaf(tm, cons, num);
            den += tm;
        }
    }
    return __fdividef(num, den);
}

// -------------------------- pass 1: per-edge attention ----------------------
// 4 edges per thread: int4 src/dst loads -> 8 outstanding float4 gathers.
__global__ void __launch_bounds__(256) edge_attention_kernel(
    const float* __restrict__ feat,
    const int*   __restrict__ src,
    const int*   __restrict__ dst,
    const float* __restrict__ mat,    // 2x9 row-major
    const float* __restrict__ bias,   // 9
    float* __restrict__ out,
    int n_edges)
{
    __shared__ float sM0[9], sM1[9], sB[9];
    int t = threadIdx.x;
    if (t < 9)       sM0[t]      = mat[t];
    else if (t < 18) sM1[t - 9]  = mat[t];
    else if (t < 27) sB[t - 18]  = bias[t - 18];
    __syncthreads();

    int n4 = n_edges >> 2;
    int k = blockIdx.x * blockDim.x + t;

    if (k < n4) {
        int4 s4 = reinterpret_cast<const int4*>(src)[k];
        int4 d4 = reinterpret_cast<const int4*>(dst)[k];

        const float4* f4 = reinterpret_cast<const float4*>(feat);
        // issue all 8 gathers up front for MLP
        float4 fs0 = __ldg(f4 + s4.x);
        float4 fs1 = __ldg(f4 + s4.y);
        float4 fs2 = __ldg(f4 + s4.z);
        float4 fs3 = __ldg(f4 + s4.w);
        float4 fd0 = __ldg(f4 + d4.x);
        float4 fd1 = __ldg(f4 + d4.y);
        float4 fd2 = __ldg(f4 + d4.z);
        float4 fd3 = __ldg(f4 + d4.w);

        float4 r;
        r.x = edge_attn(fs0, fd0, sM0, sM1, sB);
        r.y = edge_attn(fs1, fd1, sM0, sM1, sB);
        r.z = edge_attn(fs2, fd2, sM0, sM1, sB);
        r.w = edge_attn(fs3, fd3, sM0, sM1, sB);
        reinterpret_cast<float4*>(out)[k] = r;
    }

    // scalar tail (n_edges % 4 elements), handled by first few threads of blk 0
    int tail = n_edges - (n4 << 2);
    if (blockIdx.x == 0 && t < tail) {
        int e = (n4 << 2) + t;
        const float4* f4 = reinterpret_cast<const float4*>(feat);
        float4 fs = __ldg(f4 + src[e]);
        float4 fd = __ldg(f4 + dst[e]);
        out[e] = edge_attn(fs, fd, sM0, sM1, sB);
    }
}

// --------------------- online (max,sum) combine helper ----------------------
__device__ __forceinline__ void combine_ms(float& m, float& s, float mo, float so)
{
    float mn = fmaxf(m, mo);
    if (mn == -CUDART_INF_F) { m = mn; s = 0.0f; return; }
    s = s * __expf(m - mn) + so * __expf(mo - mn);
    m = mn;
}

// ------------------- pass 2a: partial softmax reduction ---------------------
__global__ void __launch_bounds__(256) softmax_reduce_kernel(
    const float* __restrict__ out,
    const int*   __restrict__ idx,
    int n_sg)
{
    int n4 = n_sg >> 2;
    float m = -CUDART_INF_F, s = 0.0f;

    for (int k = blockIdx.x * blockDim.x + threadIdx.x; k < n4;
         k += gridDim.x * blockDim.x) {
        int4 i4 = reinterpret_cast<const int4*>(idx)[k];
        float v0 = __ldg(out + i4.x);
        float v1 = __ldg(out + i4.y);
        float v2 = __ldg(out + i4.z);
        float v3 = __ldg(out + i4.w);
        float cm = fmaxf(fmaxf(v0, v1), fmaxf(v2, v3));
        float mn = fmaxf(m, cm);
        s = s * __expf(m - mn)
          + __expf(v0 - mn) + __expf(v1 - mn)
          + __expf(v2 - mn) + __expf(v3 - mn);
        m = mn;
    }

    // scalar tail
    int tail = n_sg - (n4 << 2);
    if (blockIdx.x == 0 && threadIdx.x < tail) {
        float v = __ldg(out + idx[(n4 << 2) + threadIdx.x]);
        float mn = fmaxf(m, v);
        s = s * __expf(m - mn) + __expf(v - mn);
        m = mn;
    }

    // warp reduce
    #pragma unroll
    for (int o = 16; o > 0; o >>= 1) {
        float mo = __shfl_xor_sync(0xFFFFFFFFu, m, o);
        float so = __shfl_xor_sync(0xFFFFFFFFu, s, o);
        combine_ms(m, s, mo, so);
    }
    __shared__ float sm[8], ss[8];
    int wid = threadIdx.x >> 5, lid = threadIdx.x & 31;
    if (lid == 0) { sm[wid] = m; ss[wid] = s; }
    __syncthreads();
    if (wid == 0) {
        m = (lid < 8) ? sm[lid] : -CUDART_INF_F;
        s = (lid < 8) ? ss[lid] : 0.0f;
        #pragma unroll
        for (int o = 4; o > 0; o >>= 1) {
            float mo = __shfl_xor_sync(0xFFFFFFFFu, m, o);
            float so = __shfl_xor_sync(0xFFFFFFFFu, s, o);
            combine_ms(m, s, mo, so);
        }
        if (lid == 0) {
            g_pmax[blockIdx.x] = m;
            g_psum[blockIdx.x] = s;
        }
    }
}

// -------------------- pass 2b: combine partials (1 block) -------------------
__global__ void __launch_bounds__(1024) softmax_combine_kernel()
{
    int t = threadIdx.x;
    float m = g_pmax[t];
    float s = g_psum[t];
    #pragma unroll
    for (int o = 16; o > 0; o >>= 1) {
        float mo = __shfl_xor_sync(0xFFFFFFFFu, m, o);
        float so = __shfl_xor_sync(0xFFFFFFFFu, s, o);
        combine_ms(m, s, mo, so);
    }
    __shared__ float sm[32], ss[32];
    int wid = t >> 5, lid = t & 31;
    if (lid == 0) { sm[wid] = m; ss[wid] = s; }
    __syncthreads();
    if (wid == 0) {
        m = sm[lid];
        s = ss[lid];
        #pragma unroll
        for (int o = 16; o > 0; o >>= 1) {
            float mo = __shfl_xor_sync(0xFFFFFFFFu, m, o);
            float so = __shfl_xor_sync(0xFFFFFFFFu, s, o);
            combine_ms(m, s, mo, so);
        }
        if (lid == 0) {
            g_stats[0] = m;
            g_stats[1] = 1.0f / s;
        }
    }
}

// ----------------------- pass 2c: normalize in place ------------------------
__global__ void __launch_bounds__(256) softmax_write_kernel(
    float* __restrict__ out,
    const int* __restrict__ idx,
    int n_sg)
{
    float M    = g_stats[0];
    float invS = g_stats[1];

    int n4 = n_sg >> 2;
    int k = blockIdx.x * blockDim.x + threadIdx.x;

    if (k < n4) {
        int4 i4 = reinterpret_cast<const int4*>(idx)[k];
        float v0 = out[i4.x];
        float v1 = out[i4.y];
        float v2 = out[i4.z];
        float v3 = out[i4.w];
        out[i4.x] = __expf(v0 - M) * invS;
        out[i4.y] = __expf(v1 - M) * invS;
        out[i4.z] = __expf(v2 - M) * invS;
        out[i4.w] = __expf(v3 - M) * invS;
    }

    int tail = n_sg - (n4 << 2);
    if (blockIdx.x == 0 && threadIdx.x < tail) {
        int j = idx[(n4 << 2) + threadIdx.x];
        float v = out[j];
        out[j] = __expf(v - M) * invS;
    }
}

// ---------------------------------------------------------------------------
extern "C" void kernel_launch(void* const* d_in, const int* in_sizes, int n_in,
                              void* d_out, int out_size)
{
    const float* feat = (const float*)d_in[0];
    const int*   src  = (const int*)  d_in[1];
    const int*   dst  = (const int*)  d_in[2];
    const int*   sgid = (const int*)  d_in[3];
    const float* mat  = (const float*)d_in[4];
    const float* bias = (const float*)d_in[5];
    float* out = (float*)d_out;

    int n_edges = in_sizes[1];
    int n_sg    = in_sizes[3];

    int n4e = n_edges >> 2;
    int blocks1 = (n4e + 255) / 256;
    if (blocks1 < 1) blocks1 = 1;
    edge_attention_kernel<<<blocks1, 256>>>(feat, src, dst, mat, bias, out, n_edges);

    softmax_reduce_kernel<<<NPART, 256>>>(out, sgid, n_sg);
    softmax_combine_kernel<<<1, 1024>>>();

    int n4s = n_sg >> 2;
    int blocks2 = (n4s + 255) / 256;
    if (blocks2 < 1) blocks2 = 1;
    softmax_write_kernel<<<blocks2, 256>>>(out, sgid, n_sg);
}